// round 14
// baseline (speedup 1.0000x reference)
#include <cuda_runtime.h>
#include <cstdint>

// x: [16, 64, 128, 128] (B, C, H, W), HX = HY = 64.
// Pass 1: 2048 sequences (b,h), T=128 along w.
// Pass 2: 2048 sequences (b,w), T=128 along h.

using ull = unsigned long long;

__device__ float g_pre[2048 * 128 * 64];   // [seq][t][j]
__device__ float g_mid[2048 * 128 * 64];   // [seq][t][j] (pass1 mid / pass2 staging)
__device__ float g_WTx[64 * 64];           // Wih_x^T: [c][j]
__device__ float g_WTy[64 * 64];           // Wih_y^T: [j][j2]
__device__ ull   g_bsdx[64];               // dup'd bias sums
__device__ ull   g_bsdy[64];

__device__ __forceinline__ ull ffma2(ull a, ull b, ull c) {
    ull d;
    asm("fma.rn.f32x2 %0, %1, %2, %3;" : "=l"(d) : "l"(a), "l"(b), "l"(c));
    return d;
}
__device__ __forceinline__ ull addf2(ull a, ull b) {
    ull d;
    asm("add.rn.f32x2 %0, %1, %2;" : "=l"(d) : "l"(a), "l"(b));
    return d;
}
__device__ __forceinline__ ull dup2(float x) {
    ull d;
    asm("mov.b64 %0, {%1, %1};" : "=l"(d) : "r"(__float_as_uint(x)));
    return d;
}
__device__ __forceinline__ ull pack2(float x, float y) {
    ull d;
    asm("mov.b64 %0, {%1, %2};" : "=l"(d) : "r"(__float_as_uint(x)), "r"(__float_as_uint(y)));
    return d;
}
__device__ __forceinline__ float lo_f(ull v) { return __uint_as_float((unsigned)(v & 0xffffffffull)); }
__device__ __forceinline__ float hi_f(ull v) { return __uint_as_float((unsigned)(v >> 32)); }
__device__ __forceinline__ float tanh_fast(float x) {
    float r;
    asm("tanh.approx.f32 %0, %1;" : "=f"(r) : "f"(x));
    return r;
}
__device__ __forceinline__ void cp_async16(uint32_t dst, const void* src) {
    asm volatile("cp.async.cg.shared.global [%0], [%1], 16;" :: "r"(dst), "l"(src));
}
#define CP_COMMIT() asm volatile("cp.async.commit_group;")
#define CP_WAIT(n)  asm volatile("cp.async.wait_group %0;" :: "n"(n))

// ---------------------------------------------------------------------------
// Prep.
// ---------------------------------------------------------------------------
__global__ void prep_kernel(const float* __restrict__ Wih_x,
                            const float* __restrict__ Wih_y,
                            const float* __restrict__ bih_x,
                            const float* __restrict__ bhh_x,
                            const float* __restrict__ bih_y,
                            const float* __restrict__ bhh_y) {
    int t = threadIdx.x;
    for (int e = t; e < 4096; e += 256) {
        int c = e >> 6, j = e & 63;
        g_WTx[c * 64 + j] = Wih_x[j * 64 + c];
        g_WTy[c * 64 + j] = Wih_y[j * 64 + c];
    }
    if (t < 64) {
        g_bsdx[t] = dup2(bih_x[t] + bhh_x[t]);
        g_bsdy[t] = dup2(bih_y[t] + bhh_y[t]);
    }
}

// ---------------------------------------------------------------------------
// Shared proj compute (r8-proven).
// ---------------------------------------------------------------------------
template <int PAD>
__device__ __forceinline__ void proj_compute(const float in_sh[64][PAD],
                                             const float W_sh[64][64],
                                             const ull* bsd, int tid, int row) {
    int pt = tid >> 4;    // position group of 8 (broadcast X)
    int jt = tid & 15;    // output group of 4 (conflict-free W)

    const ull* bd = bsd + jt * 4;
    ull a[4][4];
    #pragma unroll
    for (int o = 0; o < 4; o++) {
        ull bv = bd[o];
        a[0][o] = bv; a[1][o] = bv; a[2][o] = bv; a[3][o] = bv;
    }

    #pragma unroll 8
    for (int c = 0; c < 64; c++) {
        ulonglong2 X0 = *(const ulonglong2*)&in_sh[c][pt * 8];
        ulonglong2 X1 = *(const ulonglong2*)&in_sh[c][pt * 8 + 4];
        float4 wv = *(const float4*)&W_sh[c][jt * 4];
        ull w0 = dup2(wv.x), w1 = dup2(wv.y), w2 = dup2(wv.z), w3 = dup2(wv.w);
        a[0][0] = ffma2(X0.x, w0, a[0][0]);  a[1][0] = ffma2(X0.y, w0, a[1][0]);
        a[2][0] = ffma2(X1.x, w0, a[2][0]);  a[3][0] = ffma2(X1.y, w0, a[3][0]);
        a[0][1] = ffma2(X0.x, w1, a[0][1]);  a[1][1] = ffma2(X0.y, w1, a[1][1]);
        a[2][1] = ffma2(X1.x, w1, a[2][1]);  a[3][1] = ffma2(X1.y, w1, a[3][1]);
        a[0][2] = ffma2(X0.x, w2, a[0][2]);  a[1][2] = ffma2(X0.y, w2, a[1][2]);
        a[2][2] = ffma2(X1.x, w2, a[2][2]);  a[3][2] = ffma2(X1.y, w2, a[3][2]);
        a[0][3] = ffma2(X0.x, w3, a[0][3]);  a[1][3] = ffma2(X0.y, w3, a[1][3]);
        a[2][3] = ffma2(X1.x, w3, a[2][3]);  a[3][3] = ffma2(X1.y, w3, a[3][3]);
    }

    float* dst = g_pre + (size_t)row * 8192 + (pt * 8) * 64 + jt * 4;
    #pragma unroll
    for (int pp = 0; pp < 4; pp++) {
        float4 o;
        o = make_float4(lo_f(a[pp][0]), lo_f(a[pp][1]), lo_f(a[pp][2]), lo_f(a[pp][3]));
        *(float4*)(dst + (pp * 2 + 0) * 64) = o;
        o = make_float4(hi_f(a[pp][0]), hi_f(a[pp][1]), hi_f(a[pp][2]), hi_f(a[pp][3]));
        *(float4*)(dst + (pp * 2 + 1) * 64) = o;
    }
}

// ---------------------------------------------------------------------------
// proj_x (r12-exact).
// ---------------------------------------------------------------------------
__global__ __launch_bounds__(256) void proj_x_kernel(const float* __restrict__ src) {
    __shared__ float in_sh[64][128];
    __shared__ float W_sh[64][64];

    int tid = threadIdx.x;
    int row = blockIdx.x;
    int b = row >> 7, h = row & 127;
    const float* base = src + (size_t)b * 1048576 + (size_t)h * 128;

    uint32_t shW = (uint32_t)__cvta_generic_to_shared(&W_sh[0][0]);
    uint32_t shI = (uint32_t)__cvta_generic_to_shared(&in_sh[0][0]);
    {
        #pragma unroll
        for (int i = 0; i < 4; i++) {
            int e = tid + i * 256;
            cp_async16(shW + e * 16, g_WTx + e * 4);
        }
        #pragma unroll
        for (int i = 0; i < 8; i++) {
            int e = tid + i * 256;
            int c = e >> 5, g4 = e & 31;
            cp_async16(shI + e * 16, base + (size_t)c * 16384 + g4 * 4);
        }
        CP_COMMIT();
        CP_WAIT(0);
        __syncthreads();
    }
    proj_compute<128>(in_sh, W_sh, g_bsdx, tid, row);
}

// ---------------------------------------------------------------------------
// proj_y (r12-exact): input from g_mid[(b,h)][w][j] via in-register 4x4 transpose.
// ---------------------------------------------------------------------------
__global__ __launch_bounds__(256) void proj_y_kernel() {
    __shared__ float in_sh[64][132];
    __shared__ float W_sh[64][64];

    int tid = threadIdx.x;
    int row = blockIdx.x;              // b*128 + w
    int b = row >> 7, w = row & 127;
    const float* mid_base = g_mid + (size_t)b * 1048576 + (size_t)w * 64;

    uint32_t shW = (uint32_t)__cvta_generic_to_shared(&W_sh[0][0]);
    #pragma unroll
    for (int i = 0; i < 4; i++) {
        int e = tid + i * 256;
        cp_async16(shW + e * 16, g_WTy + e * 4);
    }
    CP_COMMIT();

    #pragma unroll
    for (int i = 0; i < 2; i++) {
        int tl = tid + i * 256;                  // 0..511
        int h4 = tl >> 4, j4 = tl & 15;
        const float* p = mid_base + (size_t)(h4 * 4) * 8192 + j4 * 4;
        float4 r0 = *(const float4*)(p + 0 * 8192);
        float4 r1 = *(const float4*)(p + 1 * 8192);
        float4 r2 = *(const float4*)(p + 2 * 8192);
        float4 r3 = *(const float4*)(p + 3 * 8192);
        *(float4*)&in_sh[j4 * 4 + 0][h4 * 4] = make_float4(r0.x, r1.x, r2.x, r3.x);
        *(float4*)&in_sh[j4 * 4 + 1][h4 * 4] = make_float4(r0.y, r1.y, r2.y, r3.y);
        *(float4*)&in_sh[j4 * 4 + 2][h4 * 4] = make_float4(r0.z, r1.z, r2.z, r3.z);
        *(float4*)&in_sh[j4 * 4 + 3][h4 * 4] = make_float4(r0.w, r1.w, r2.w, r3.w);
    }
    CP_WAIT(0);
    __syncthreads();

    proj_compute<132>(in_sh, W_sh, g_bsdy, tid, row);
}

// ---------------------------------------------------------------------------
// Warp-autonomous scan: ONE sequence per 32-thread block, no block barriers.
// Reads g_pre, writes g_mid (device globals referenced INSIDE device code).
// Lane l owns outputs j = 2l, 2l+1 (Whh rows as 64 k-pair ulls, reg-resident).
// h as lane-packed pairs in double-buffered smem; per step: 16 LDS.128
// broadcasts + 64 FFMA2 + 2 tanh + STS.64 + __syncwarp. 2-step LDG prefetch.
// ---------------------------------------------------------------------------
__device__ __forceinline__ void scan_step(int t, ull pv, ull* hsh_cur, ull* hsh_nxt,
                                          const ull* Wa, const ull* Wb,
                                          float* outp, int l) {
    const ulonglong2* hq = (const ulonglong2*)hsh_cur;
    ull aA = 0, aB = 0, aC = 0, aD = 0;
    #pragma unroll
    for (int m = 0; m < 16; m++) {
        ulonglong2 q = hq[m];                 // (h[4m],h[4m+1]), (h[4m+2],h[4m+3])
        aA = ffma2(q.x, Wa[2 * m],     aA);
        aB = ffma2(q.y, Wa[2 * m + 1], aB);
        aC = ffma2(q.x, Wb[2 * m],     aC);
        aD = ffma2(q.y, Wb[2 * m + 1], aD);
    }
    ull sA = addf2(aA, aB);
    ull sC = addf2(aC, aD);
    float y0 = lo_f(pv) + lo_f(sA) + hi_f(sA);
    float y1 = hi_f(pv) + lo_f(sC) + hi_f(sC);
    ull hn = pack2(tanh_fast(y0), tanh_fast(y1));
    *(ull*)(outp + (size_t)t * 64) = hn;
    hsh_nxt[l] = hn;
    __syncwarp();
}

__global__ __launch_bounds__(32, 12) void scan_warp_kernel(const float* __restrict__ Whh) {
    __shared__ ull hsh[2][32];

    int l   = threadIdx.x;
    int seq = blockIdx.x;

    const float* prep_ = g_pre + (size_t)seq * 8192 + 2 * l;
    float* outp        = g_mid + (size_t)seq * 8192 + 2 * l;

    // Whh rows 2l, 2l+1 as k-pair ulls
    ull Wa[32], Wb[32];
    {
        const ull* ra = (const ull*)(Whh + (2 * l) * 64);
        const ull* rb = (const ull*)(Whh + (2 * l + 1) * 64);
        #pragma unroll
        for (int m = 0; m < 32; m++) { Wa[m] = ra[m]; Wb[m] = rb[m]; }
    }

    hsh[0][l] = 0;
    __syncwarp();

    // 2-step prefetch ring
    ull r0 = *(const ull*)(prep_ + 0 * 64);
    ull r1 = *(const ull*)(prep_ + 1 * 64);

    #pragma unroll 1
    for (int tb = 0; tb < 128; tb += 2) {
        ull p0 = r0, p1 = r1;
        if (tb + 2 < 128) {
            r0 = *(const ull*)(prep_ + (size_t)(tb + 2) * 64);
            r1 = *(const ull*)(prep_ + (size_t)(tb + 3) * 64);
        }
        scan_step(tb + 0, p0, hsh[0], hsh[1], Wa, Wb, outp, l);
        scan_step(tb + 1, p1, hsh[1], hsh[0], Wa, Wb, outp, l);
    }
}

// ---------------------------------------------------------------------------
// Transpose epilogue: g_mid[(b,w)][t=h][j] -> out[b][j][h][w].
// Tile 8h x 8w x 64j; coalesced reads, dense 32B output segments.
// ---------------------------------------------------------------------------
__global__ __launch_bounds__(256) void transpose_kernel(float* __restrict__ out) {
    __shared__ float tile[8][8][68];   // [ti(h)][wi][j], pad 68

    int tid = threadIdx.x;
    int blk = blockIdx.x;              // b*256 + tt*16 + wt
    int b  = blk >> 8;
    int tt = (blk >> 4) & 15;
    int wt = blk & 15;

    const float* src = g_mid + (size_t)(b * 128 + wt * 8) * 8192 + (size_t)(tt * 8) * 64;

    #pragma unroll
    for (int i = 0; i < 4; i++) {
        int e = tid + i * 256;                 // 0..1023 granules
        int row = e >> 4;
        int ti = row >> 3, wi = row & 7;
        int j4 = e & 15;
        float4 v = *(const float4*)(src + (size_t)wi * 8192 + ti * 64 + j4 * 4);
        *(float4*)&tile[ti][wi][j4 * 4] = v;
    }
    __syncthreads();

    #pragma unroll
    for (int i = 0; i < 2; i++) {
        int task = tid + i * 256;              // 0..511
        int ti = task >> 6;
        int j  = task & 63;
        float4 v0, v1;
        v0.x = tile[ti][0][j]; v0.y = tile[ti][1][j];
        v0.z = tile[ti][2][j]; v0.w = tile[ti][3][j];
        v1.x = tile[ti][4][j]; v1.y = tile[ti][5][j];
        v1.z = tile[ti][6][j]; v1.w = tile[ti][7][j];
        float* d = out + (size_t)b * 1048576 + (size_t)j * 16384
                 + (size_t)(tt * 8 + ti) * 128 + wt * 8;
        *(float4*)(d)     = v0;
        *(float4*)(d + 4) = v1;
    }
}

// ---------------------------------------------------------------------------
extern "C" void kernel_launch(void* const* d_in, const int* in_sizes, int n_in,
                              void* d_out, int out_size) {
    const float* x     = (const float*)d_in[0];
    const float* Wih_x = (const float*)d_in[1];
    const float* Whh_x = (const float*)d_in[2];
    const float* bih_x = (const float*)d_in[3];
    const float* bhh_x = (const float*)d_in[4];
    const float* Wih_y = (const float*)d_in[5];
    const float* Whh_y = (const float*)d_in[6];
    const float* bih_y = (const float*)d_in[7];
    const float* bhh_y = (const float*)d_in[8];
    float* out = (float*)d_out;

    prep_kernel<<<1, 256>>>(Wih_x, Wih_y, bih_x, bhh_x, bih_y, bhh_y);
    proj_x_kernel<<<2048, 256>>>(x);               // pre_x [(b,h)][w][j]
    scan_warp_kernel<<<2048, 32>>>(Whh_x);         // scan w: g_pre -> g_mid
    proj_y_kernel<<<2048, 256>>>();                // pre_y [(b,w)][h][j2]
    scan_warp_kernel<<<2048, 32>>>(Whh_y);         // scan h: g_pre -> g_mid
    transpose_kernel<<<4096, 256>>>(out);          // -> out [b][j][h][w]
}